// round 1
// baseline (speedup 1.0000x reference)
#include <cuda_runtime.h>
#include <cuda_bf16.h>
#include <cstdint>

// SimplifiedMambaBlock — analytical reduction:
//   h0 = 0 and the scan step is h = A_t * h (multiplicative only, no input
//   injection), so h ≡ 0, ssm_out ≡ 0, y ≡ 0, out = einsum(0, W) = 0, and
//   the reference returns out + residual == x bit-exactly.
// The optimal kernel is therefore a bandwidth-limited device copy of x.

__global__ void __launch_bounds__(256)
identity_copy_vec4(const float4* __restrict__ src, float4* __restrict__ dst,
                   long long n_vec4)
{
    long long i = (long long)blockIdx.x * blockDim.x + threadIdx.x;
    long long stride = (long long)gridDim.x * blockDim.x;
    for (; i < n_vec4; i += stride) {
        dst[i] = src[i];
    }
}

__global__ void __launch_bounds__(256)
identity_copy_tail(const float* __restrict__ src, float* __restrict__ dst,
                   long long start, long long n)
{
    long long i = start + (long long)blockIdx.x * blockDim.x + threadIdx.x;
    if (i < n) dst[i] = src[i];
}

extern "C" void kernel_launch(void* const* d_in, const int* in_sizes, int n_in,
                              void* d_out, int out_size)
{
    const float* x = (const float*)d_in[0];   // metadata order: x first
    float* out = (float*)d_out;

    long long n = (long long)out_size;        // 8*2048*512 = 8,388,608 fp32
    long long n_vec4 = n >> 2;                // 2,097,152 float4
    long long tail_start = n_vec4 << 2;

    if (n_vec4 > 0) {
        // One float4 per thread per pass; size grid so each thread does ~2
        // iterations — keeps high MLP without launch overhead of huge grids.
        int threads = 256;
        long long want_blocks = (n_vec4 + threads - 1) / threads;
        int blocks = (int)(want_blocks > 8192 ? 8192 : want_blocks);
        identity_copy_vec4<<<blocks, threads>>>(
            (const float4*)x, (float4*)out, n_vec4);
    }
    if (tail_start < n) {
        long long tail = n - tail_start;
        int threads = 256;
        int blocks = (int)((tail + threads - 1) / threads);
        identity_copy_tail<<<blocks, threads>>>(x, out, tail_start, n);
    }
}

// round 4
// speedup vs baseline: 1.0030x; 1.0030x over previous
#include <cuda_runtime.h>
#include <cstdint>

// SimplifiedMambaBlock — analytical identity:
//   h0 = 0 and the scan is purely multiplicative (h = A_t * h, no input
//   injection), so h ≡ 0 → ssm_out ≡ 0 → y ≡ 0 → out = 0, and the reference
//   returns residual == x bit-exactly. Optimal kernel = device copy of x.
//
// R2: 256-bit ld/st (sm_100+ v8.b32), MLP=2 per thread, 32-bit indexing,
// exact grid (no grid-stride loop) — relieve the LSU-issue/ALU bound seen
// in R1 (alu=31.5%, issue=59%, nothing saturated).

__device__ __forceinline__ void ldg_v8(const unsigned* p, unsigned r[8]) {
    asm volatile("ld.global.v8.b32 {%0,%1,%2,%3,%4,%5,%6,%7}, [%8];"
                 : "=r"(r[0]), "=r"(r[1]), "=r"(r[2]), "=r"(r[3]),
                   "=r"(r[4]), "=r"(r[5]), "=r"(r[6]), "=r"(r[7])
                 : "l"(p));
}

__device__ __forceinline__ void stg_v8(unsigned* p, const unsigned r[8]) {
    asm volatile("st.global.v8.b32 [%0], {%1,%2,%3,%4,%5,%6,%7,%8};"
                 :: "l"(p),
                    "r"(r[0]), "r"(r[1]), "r"(r[2]), "r"(r[3]),
                    "r"(r[4]), "r"(r[5]), "r"(r[6]), "r"(r[7])
                 : "memory");
}

// Each thread copies two 32B chunks (chunk gid and gid+nthreads), loads
// batched before stores for MLP=2.
__global__ void __launch_bounds__(256)
copy_v8x2(const unsigned* __restrict__ src, unsigned* __restrict__ dst,
          unsigned n_chunks)
{
    unsigned gid = blockIdx.x * 256u + threadIdx.x;
    unsigned nthreads = gridDim.x * 256u;
    unsigned i0 = gid;
    unsigned i1 = gid + nthreads;

    unsigned a[8], b[8];
    if (i1 < n_chunks) {
        ldg_v8(src + (size_t)i0 * 8u, a);
        ldg_v8(src + (size_t)i1 * 8u, b);
        stg_v8(dst + (size_t)i0 * 8u, a);
        stg_v8(dst + (size_t)i1 * 8u, b);
    } else if (i0 < n_chunks) {
        ldg_v8(src + (size_t)i0 * 8u, a);
        stg_v8(dst + (size_t)i0 * 8u, a);
    }
}

__global__ void __launch_bounds__(256)
copy_tail(const float* __restrict__ src, float* __restrict__ dst,
          unsigned start, unsigned n)
{
    unsigned i = start + blockIdx.x * 256u + threadIdx.x;
    if (i < n) dst[i] = src[i];
}

extern "C" void kernel_launch(void* const* d_in, const int* in_sizes, int n_in,
                              void* d_out, int out_size)
{
    const float* x = (const float*)d_in[0];   // metadata order: x first
    float* out = (float*)d_out;

    unsigned n = (unsigned)out_size;          // 8*2048*512 = 8,388,608 fp32
    unsigned n_chunks = n >> 3;               // 32B chunks: 1,048,576
    unsigned tail_start = n_chunks << 3;

    if (n_chunks > 0) {
        // 2 chunks per thread → total threads = ceil(n_chunks/2)
        unsigned threads_needed = (n_chunks + 1) >> 1;   // 524,288
        unsigned blocks = (threads_needed + 255u) >> 8;  // 2048
        copy_v8x2<<<blocks, 256>>>((const unsigned*)x, (unsigned*)out, n_chunks);
    }
    if (tail_start < n) {
        unsigned tail = n - tail_start;
        unsigned blocks = (tail + 255u) >> 8;
        copy_tail<<<blocks, 256>>>(x, out, tail_start, n);
    }
}